// round 5
// baseline (speedup 1.0000x reference)
#include <cuda_runtime.h>
#include <cuda_bf16.h>
#include <math.h>
#include <stdint.h>

#define BB   128
#define TL   2048
#define HH   200
#define HP   256
#define NKCH 7         // k chunks of 32 (K padded 224)
#define NPB  256       // padded N for B tile
#define NCTX 16        // context t-chunks (2048/128)

// ---------------- device scratch ----------------
__device__ float d_qp[BB * HP];                 // q@Wa.T + ba + bua (padded 0)
__device__ float d_Vap[HP];                     // Va padded (0 beyond 200)
// B pre-chunked gmem image identical to smem chunk layout: [ch][n(256)][40 halves]
__device__ __align__(16) unsigned short d_Bbf[NKCH * NPB * 40];
__device__ float d_scores[BB * TL];
__device__ float d_ctxp[BB * NCTX * HH];

// ---------------- helpers ----------------
__device__ __forceinline__ float tanha(float x) {
    float y; asm("tanh.approx.f32 %0, %1;" : "=f"(y) : "f"(x)); return y;
}
__device__ __forceinline__ float sigf(float x) { return 1.0f / (1.0f + __expf(-x)); }
__device__ __forceinline__ uint32_t smem_u32(const void* p) {
    uint32_t a;
    asm("{ .reg .u64 t; cvta.to.shared.u64 t, %1; cvt.u32.u64 %0, t; }" : "=r"(a) : "l"(p));
    return a;
}
__device__ __forceinline__ void cp16(uint32_t dst, const void* src) {
    asm volatile("cp.async.ca.shared.global [%0], [%1], 16;" :: "r"(dst), "l"(src) : "memory");
}
__device__ __forceinline__ uint32_t packbf(float lo, float hi) {
    uint32_t r; asm("cvt.rn.bf16x2.f32 %0, %1, %2;" : "=r"(r) : "f"(hi), "f"(lo)); return r;
}
__device__ __forceinline__ void mma_bf16(float* c, const uint32_t* a, uint32_t b0, uint32_t b1) {
    asm volatile("mma.sync.aligned.m16n8k16.row.col.f32.bf16.bf16.f32 "
                 "{%0,%1,%2,%3}, {%4,%5,%6,%7}, {%8,%9}, {%0,%1,%2,%3};"
                 : "+f"(c[0]), "+f"(c[1]), "+f"(c[2]), "+f"(c[3])
                 : "r"(a[0]), "r"(a[1]), "r"(a[2]), "r"(a[3]), "r"(b0), "r"(b1));
}
__device__ __forceinline__ void ldsm4(uint32_t* r, uint32_t addr) {
    asm volatile("ldmatrix.sync.aligned.m8n8.x4.shared.b16 {%0,%1,%2,%3}, [%4];"
                 : "=r"(r[0]), "=r"(r[1]), "=r"(r[2]), "=r"(r[3]) : "r"(addr));
}

// SMEM layout (bytes): qp 1K | Va 1K | red 2K | A 2x10240 | B 2x20480
#define SM_QP  0
#define SM_VA  1024
#define SM_RED 2048
#define SM_A   4096
#define SM_B   24576
#define SMEM_SZ 65536

extern __shared__ char sm_dyn[];

// ---------------- 1) setup ----------------
__global__ void setup_kernel(const float* __restrict__ h0,
                             const float* __restrict__ Wa,
                             const float* __restrict__ ba,
                             const float* __restrict__ Ua,
                             const float* __restrict__ bua,
                             const float* __restrict__ Va) {
    int blk = blockIdx.x;
    int tid = threadIdx.x;
    int lane = tid & 31, wid = tid >> 5;
    if (blk < BB) {
        // qp[b][h] = ba[h]+bua[h] + Wa[h,:]@h0[b]; warp-per-h
        __shared__ float q[HH];
        for (int k = tid; k < HH; k += 256) q[k] = h0[blk * HH + k];
        __syncthreads();
        for (int h = wid; h < HP; h += 8) {
            if (h < HH) {
                float acc = 0.f;
                const float* w = Wa + h * HH;
                for (int k = lane; k < HH; k += 32) acc += w[k] * q[k];
                #pragma unroll
                for (int o = 16; o; o >>= 1) acc += __shfl_xor_sync(0xffffffffu, acc, o);
                if (lane == 0) d_qp[blk * HP + h] = acc + ba[h] + bua[h];
            } else if (lane == 0) d_qp[blk * HP + h] = 0.f;
        }
    } else if (blk < BB + 32) {
        // B image: [ch][n][40], 71680 elems over 32 blocks
        int part = blk - BB;
        for (int idx = part * 2240 + tid; idx < (part + 1) * 2240; idx += 256) {
            int ch = idx / (NPB * 40);
            int rem = idx - ch * NPB * 40;
            int n = rem / 40, hh = rem - n * 40;
            int k = ch * 32 + hh;
            float v = (hh < 32 && n < HH && k < HH) ? Ua[n * HH + k] : 0.0f;
            __nv_bfloat16 bv = __float2bfloat16(v);
            d_Bbf[idx] = *(unsigned short*)&bv;
        }
    } else {
        for (int h = tid; h < HP; h += 256)
            d_Vap[h] = (h < HH) ? Va[h] : 0.0f;
    }
}

// ---------------- 2) scores via ldmatrix + bf16 mma ----------------
__global__ void __launch_bounds__(512, 1)
scores_mma_kernel(const float* __restrict__ enc) {
    char* smem = sm_dyn;
    uint32_t sb = smem_u32(smem);
    int tid  = threadIdx.x;
    int lane = tid & 31;
    int wid  = tid >> 5;
    int wm   = wid & 3;     // M warps (32 rows each)
    int wn   = wid >> 2;    // N warps (64 cols each)
    int b    = blockIdx.y;
    int t0   = blockIdx.x * 128;

    if (tid < 256) {
        ((float*)(smem + SM_QP))[tid] = d_qp[b * HP + tid];
        ((float*)(smem + SM_VA))[tid] = d_Vap[tid];
    }

    const float* encb = enc + ((long)b * TL + t0) * HH;

    // stage B chunk 0
    for (int i = tid; i < 1280; i += 512)
        cp16(sb + SM_B + i * 16, (const char*)d_Bbf + i * 16);
    asm volatile("cp.async.commit_group;" ::: "memory");

    // A chunk regs (thread: m=tid>>2, kq=tid&3 -> 8 floats)
    int am = tid >> 2, akq = tid & 3;
    float4 f0, f1;
    {
        int k = akq * 8;
        f0 = *(const float4*)(encb + (long)am * HH + k);
        f1 = *(const float4*)(encb + (long)am * HH + k + 4);
    }

    float acc[2][8][4];
    #pragma unroll
    for (int mt = 0; mt < 2; mt++)
        #pragma unroll
        for (int nt = 0; nt < 8; nt++)
            #pragma unroll
            for (int j = 0; j < 4; j++) acc[mt][nt][j] = 0.0f;

    int arow  = (lane & 7) + ((lane >> 3) & 1) * 8;
    int akoff = (lane >> 4) * 16;
    int brow  = (lane & 7) + ((lane >> 4) << 3);
    int bkoff = ((lane >> 3) & 1) * 16;

    #pragma unroll 1
    for (int ch = 0; ch < NKCH; ch++) {
        int buf = ch & 1;
        // STS current A chunk (bf16, stride 80B rows)
        {
            uint4 p;
            p.x = packbf(f0.x, f0.y); p.y = packbf(f0.z, f0.w);
            p.z = packbf(f1.x, f1.y); p.w = packbf(f1.z, f1.w);
            *(uint4*)(smem + SM_A + buf * 10240 + am * 80 + akq * 16) = p;
        }
        if (ch + 1 < NKCH) {
            // prefetch next A chunk into regs
            int k = (ch + 1) * 32 + akq * 8;
            if (ch + 1 < 6 || akq == 0) {
                f0 = *(const float4*)(encb + (long)am * HH + k);
                f1 = *(const float4*)(encb + (long)am * HH + k + 4);
            } else {
                f0 = make_float4(0.f, 0.f, 0.f, 0.f);
                f1 = make_float4(0.f, 0.f, 0.f, 0.f);
            }
            // stage next B chunk
            uint32_t dst = sb + SM_B + (buf ^ 1) * 20480;
            const char* src = (const char*)d_Bbf + (ch + 1) * 20480;
            for (int i = tid; i < 1280; i += 512) cp16(dst + i * 16, src + i * 16);
            asm volatile("cp.async.commit_group;" ::: "memory");
            asm volatile("cp.async.wait_group 1;" ::: "memory");
        } else {
            asm volatile("cp.async.wait_group 0;" ::: "memory");
        }
        __syncthreads();

        uint32_t abase = sb + SM_A + buf * 10240;
        uint32_t bbase = sb + SM_B + buf * 20480;
        #pragma unroll
        for (int ks = 0; ks < 2; ks++) {
            uint32_t a[2][4];
            #pragma unroll
            for (int mt = 0; mt < 2; mt++)
                ldsm4(a[mt], abase + (wm * 32 + mt * 16 + arow) * 80 + akoff + ks * 32);
            uint32_t bf[8][2];
            #pragma unroll
            for (int j = 0; j < 4; j++) {
                uint32_t r[4];
                ldsm4(r, bbase + (wn * 64 + j * 16 + brow) * 80 + bkoff + ks * 32);
                bf[2 * j][0] = r[0]; bf[2 * j][1] = r[1];
                bf[2 * j + 1][0] = r[2]; bf[2 * j + 1][1] = r[3];
            }
            #pragma unroll
            for (int mt = 0; mt < 2; mt++)
                #pragma unroll
                for (int nt = 0; nt < 8; nt++)
                    mma_bf16(acc[mt][nt], a[mt], bf[nt][0], bf[nt][1]);
        }
        __syncthreads();
    }

    // ---- epilogue: per-row sum_h Va[h]*tanh(qp[h]+e) ----
    const float* qpS = (const float*)(smem + SM_QP);
    const float* VaS = (const float*)(smem + SM_VA);
    float rs[4] = {0.f, 0.f, 0.f, 0.f};
    int cpair = (lane & 3) * 2;
    #pragma unroll
    for (int mt = 0; mt < 2; mt++) {
        #pragma unroll
        for (int nt = 0; nt < 8; nt++) {
            int h0 = wn * 64 + nt * 8 + cpair;
            float va0 = VaS[h0], va1 = VaS[h0 + 1];
            float q0 = qpS[h0], q1 = qpS[h0 + 1];
            float* cc = acc[mt][nt];
            rs[mt * 2 + 0] += va0 * tanha(q0 + cc[0]) + va1 * tanha(q1 + cc[1]);
            rs[mt * 2 + 1] += va0 * tanha(q0 + cc[2]) + va1 * tanha(q1 + cc[3]);
        }
    }
    #pragma unroll
    for (int j = 0; j < 4; j++) {
        rs[j] += __shfl_xor_sync(0xffffffffu, rs[j], 1);
        rs[j] += __shfl_xor_sync(0xffffffffu, rs[j], 2);
    }
    float* red = (float*)(smem + SM_RED);
    if ((lane & 3) == 0) {
        int q = lane >> 2;
        red[wn * 128 + wm * 32 + q]      = rs[0];
        red[wn * 128 + wm * 32 + q + 8]  = rs[1];
        red[wn * 128 + wm * 32 + q + 16] = rs[2];
        red[wn * 128 + wm * 32 + q + 24] = rs[3];
    }
    __syncthreads();
    if (tid < 128) {
        float s = red[tid] + red[128 + tid] + red[256 + tid] + red[384 + tid];
        d_scores[(long)b * TL + t0 + tid] = s;   // bva shift cancels in softmax
    }
}

// ---------------- 3) softmax over T, in place ----------------
__global__ void softmax_kernel() {
    __shared__ float red[256];
    int b = blockIdx.x, tid = threadIdx.x;
    float* row = d_scores + (long)b * TL;

    float m = -1e30f;
    for (int i = tid; i < TL; i += 256) m = fmaxf(m, row[i]);
    red[tid] = m; __syncthreads();
    for (int s = 128; s; s >>= 1) { if (tid < s) red[tid] = fmaxf(red[tid], red[tid + s]); __syncthreads(); }
    m = red[0]; __syncthreads();

    float sum = 0.0f;
    for (int i = tid; i < TL; i += 256) {
        float e = __expf(row[i] - m);
        row[i] = e; sum += e;
    }
    red[tid] = sum; __syncthreads();
    for (int s = 128; s; s >>= 1) { if (tid < s) red[tid] += red[tid + s]; __syncthreads(); }
    float inv = 1.0f / red[0];

    for (int i = tid; i < TL; i += 256) row[i] *= inv;
}

// ---------------- 4) context = attn @ enc (16 t-chunks of 128) ----------------
__global__ void context_kernel(const float* __restrict__ enc) {
    __shared__ float at[128];
    int tc = blockIdx.x;
    int b  = blockIdx.y;
    int tid = threadIdx.x;
    if (tid < 128) at[tid] = d_scores[(long)b * TL + tc * 128 + tid];
    __syncthreads();
    if (tid < HH) {
        const float* e = enc + ((long)b * TL + tc * 128) * HH + tid;
        float a0 = 0, a1 = 0, a2 = 0, a3 = 0, a4 = 0, a5 = 0, a6 = 0, a7 = 0;
        #pragma unroll 2
        for (int t = 0; t < 128; t += 8) {
            a0 += at[t]     * e[(long)t * HH];
            a1 += at[t + 1] * e[(long)(t + 1) * HH];
            a2 += at[t + 2] * e[(long)(t + 2) * HH];
            a3 += at[t + 3] * e[(long)(t + 3) * HH];
            a4 += at[t + 4] * e[(long)(t + 4) * HH];
            a5 += at[t + 5] * e[(long)(t + 5) * HH];
            a6 += at[t + 6] * e[(long)(t + 6) * HH];
            a7 += at[t + 7] * e[(long)(t + 7) * HH];
        }
        d_ctxp[((long)b * NCTX + tc) * HH + tid] =
            ((a0 + a1) + (a2 + a3)) + ((a4 + a5) + (a6 + a7));
    }
}

// ---------------- 5) decoder: combine + 5 LSTM+MLP steps, 4 b per block ----------------
__global__ void __launch_bounds__(256) decoder_kernel(
        const float* __restrict__ x,
        const float* __restrict__ h0,
        const float* __restrict__ c0,
        const float* __restrict__ W_ih,
        const float* __restrict__ W_hh,
        const float* __restrict__ b_ih,
        const float* __restrict__ b_hh,
        const float* __restrict__ W1, const float* __restrict__ b1,
        const float* __restrict__ W2, const float* __restrict__ b2,
        const float* __restrict__ W3, const float* __restrict__ b3,
        float* __restrict__ out) {
    __shared__ float ctx4[4][HH];
    __shared__ float h04[4][HH];
    __shared__ float gb4[4][800];
    __shared__ float r[HH];
    __shared__ float s1[100];
    __shared__ float s2[64];
    __shared__ float xb;
    int tid = threadIdx.x;
    int bs0 = blockIdx.x * 4;

    for (int bl = 0; bl < 4; bl++) {
        int b = bs0 + bl;
        if (tid < HH) {
            float s = 0.f;
            #pragma unroll
            for (int i = 0; i < NCTX; i++)
                s += d_ctxp[((long)b * NCTX + i) * HH + tid];
            ctx4[bl][tid] = s;
        }
    }
    for (int i = tid; i < 4 * HH; i += 256)
        h04[i / HH][i % HH] = h0[(bs0 + i / HH) * HH + i % HH];
    __syncthreads();

    for (int g = tid; g < 800; g += 256) {
        float bias = b_ih[g] + b_hh[g];
        float a0 = bias, a1 = bias, a2 = bias, a3 = bias;
        const float* wh = W_hh + g * HH;
        #pragma unroll 4
        for (int k = 0; k < HH; k++) {
            float wv = wh[k];
            a0 += wv * h04[0][k]; a1 += wv * h04[1][k];
            a2 += wv * h04[2][k]; a3 += wv * h04[3][k];
        }
        const float* wi = W_ih + g * 201 + 1;
        #pragma unroll 4
        for (int k = 0; k < HH; k++) {
            float wv = wi[k];
            a0 += wv * ctx4[0][k]; a1 += wv * ctx4[1][k];
            a2 += wv * ctx4[2][k]; a3 += wv * ctx4[3][k];
        }
        gb4[0][g] = a0; gb4[1][g] = a1; gb4[2][g] = a2; gb4[3][g] = a3;
    }
    __syncthreads();

    for (int bl = 0; bl < 4; bl++) {
        int b = bs0 + bl;
        if (tid == 0) xb = x[b];
        __syncthreads();
        for (int step = 0; step < 5; step++) {
            if (tid < HH) {
                float xv = xb;
                float gi = gb4[bl][tid]       + W_ih[tid * 201]         * xv;
                float gf = gb4[bl][200 + tid] + W_ih[(200 + tid) * 201] * xv;
                float gg = gb4[bl][400 + tid] + W_ih[(400 + tid) * 201] * xv;
                float go = gb4[bl][600 + tid] + W_ih[(600 + tid) * 201] * xv;
                float cp = c0[b * HH + tid];
                float cn = sigf(gf) * cp + sigf(gi) * tanhf(gg);
                float hn = sigf(go) * tanhf(cn);
                r[tid] = fmaxf(hn, 0.0f);
            }
            __syncthreads();
            if (tid < 100) {
                float acc = b1[tid];
                const float* wr = W1 + tid * HH;
                #pragma unroll 4
                for (int k = 0; k < HH; k++) acc += wr[k] * r[k];
                s1[tid] = fmaxf(acc, 0.0f);
            }
            __syncthreads();
            if (tid < 50) {
                float acc = b2[tid];
                const float* wr = W2 + tid * 100;
                #pragma unroll 4
                for (int k = 0; k < 100; k++) acc += wr[k] * s1[k];
                s2[tid] = fmaxf(acc, 0.0f);
            }
            __syncthreads();
            if (tid == 0) {
                float acc = b3[0];
                #pragma unroll
                for (int k = 0; k < 50; k++) acc += W3[k] * s2[k];
                out[b * 5 + step] = acc;
                xb = acc;
            }
            __syncthreads();
        }
    }
}

// ---------------- launch ----------------
extern "C" void kernel_launch(void* const* d_in, const int* in_sizes, int n_in,
                              void* d_out, int out_size) {
    const float* x    = (const float*)d_in[0];
    const float* h0   = (const float*)d_in[1];
    const float* c0   = (const float*)d_in[2];
    const float* enc  = (const float*)d_in[3];
    const float* Wa   = (const float*)d_in[4];
    const float* ba   = (const float*)d_in[5];
    const float* Ua   = (const float*)d_in[6];
    const float* bua  = (const float*)d_in[7];
    const float* Va   = (const float*)d_in[8];
    const float* bva  = (const float*)d_in[9];
    const float* W_ih = (const float*)d_in[10];
    const float* W_hh = (const float*)d_in[11];
    const float* b_ih = (const float*)d_in[12];
    const float* b_hh = (const float*)d_in[13];
    const float* W1   = (const float*)d_in[14];
    const float* b1   = (const float*)d_in[15];
    const float* W2   = (const float*)d_in[16];
    const float* b2   = (const float*)d_in[17];
    const float* W3   = (const float*)d_in[18];
    const float* b3   = (const float*)d_in[19];
    float* out = (float*)d_out;
    (void)bva;

    cudaFuncSetAttribute(scores_mma_kernel,
                         cudaFuncAttributeMaxDynamicSharedMemorySize, SMEM_SZ);

    setup_kernel<<<BB + 33, 256>>>(h0, Wa, ba, Ua, bua, Va);
    scores_mma_kernel<<<dim3(TL / 128, BB), 512, SMEM_SZ>>>(enc);
    softmax_kernel<<<BB, 256>>>();
    context_kernel<<<dim3(NCTX, BB), 256>>>(enc);
    decoder_kernel<<<BB / 4, 256>>>(x, h0, c0, W_ih, W_hh, b_ih, b_hh,
                                    W1, b1, W2, b2, W3, b3, out);
}